// round 13
// baseline (speedup 1.0000x reference)
#include <cuda_runtime.h>
#include <cuda_fp16.h>
#include <cstdint>

#define BB 4
#define NN 8192
#define DD 1024
#define HH 8
#define DK 128
#define BN (BB*NN)
#define SPLITS 16
#define CHS (NN/SPLITS)
#define EPSF 1e-5f
#define NKC (DD/64)
#define A_STAGE 16384u
#define B_BASE  32768u
#define GEMM_SMEM 81920
#define SC_SMEM  49152

// Scratch (allocation-free device globals)
__device__ __half g_hWk[(size_t)DD*DD];
__device__ __half g_hWv[(size_t)DD*DD];
__device__ __half g_Knh[(size_t)BB*HH*NN*DK];
__device__ __half g_Vnh[(size_t)BB*HH*NN*DK];
__device__ float  g_Spart[(size_t)SPLITS*BB*HH*DK*DK];
__device__ __half g_WeffTh[(size_t)BB*DD*DD];
__device__ float  g_beff[(size_t)BB*DD];

// ---------------------------------------------------------------------------
__device__ __forceinline__ uint32_t smem_u32(const void* p) {
    uint32_t a;
    asm("{ .reg .u64 t; cvta.to.shared.u64 t, %1; cvt.u32.u64 %0, t; }"
        : "=r"(a) : "l"(p));
    return a;
}
__device__ __forceinline__ void cp16(uint32_t smem, const void* g) {
    asm volatile("cp.async.cg.shared.global [%0], [%1], 16;"
                 :: "r"(smem), "l"(g));
}
#define CP_COMMIT() asm volatile("cp.async.commit_group;" ::: "memory")
#define CP_WAIT(n)  asm volatile("cp.async.wait_group %0;" :: "n"(n) : "memory")

__device__ __forceinline__ void ldsm4(uint32_t* r, uint32_t a) {
    asm volatile("ldmatrix.sync.aligned.m8n8.x4.shared.b16 {%0,%1,%2,%3}, [%4];"
                 : "=r"(r[0]), "=r"(r[1]), "=r"(r[2]), "=r"(r[3]) : "r"(a));
}
__device__ __forceinline__ void ldsm4t(uint32_t* r, uint32_t a) {
    asm volatile("ldmatrix.sync.aligned.m8n8.x4.trans.shared.b16 {%0,%1,%2,%3}, [%4];"
                 : "=r"(r[0]), "=r"(r[1]), "=r"(r[2]), "=r"(r[3]) : "r"(a));
}
__device__ __forceinline__ void mma16(float* d, const uint32_t* a, const uint32_t* b) {
    asm volatile(
        "mma.sync.aligned.m16n8k16.row.col.f32.f16.f16.f32 "
        "{%0,%1,%2,%3}, {%4,%5,%6,%7}, {%8,%9}, {%0,%1,%2,%3};"
        : "+f"(d[0]), "+f"(d[1]), "+f"(d[2]), "+f"(d[3])
        : "r"(a[0]), "r"(a[1]), "r"(a[2]), "r"(a[3]), "r"(b[0]), "r"(b[1]));
}
__device__ __forceinline__ uint32_t packh2(float x, float y) {
    uint32_t r;
    asm("cvt.rn.f16x2.f32 %0, %2, %1;" : "=r"(r) : "f"(x), "f"(y));
    return r;
}

// ---------------------------------------------------------------------------
__global__ __launch_bounds__(256)
void f2h_w(const float* __restrict__ Wk, const float* __restrict__ Wv, int n8)
{
    int i = blockIdx.x * 256 + threadIdx.x;
    const float* in = (i < n8) ? Wk : Wv;
    __half* out = (i < n8) ? g_hWk : g_hWv;
    int idx = (i < n8) ? i : i - n8;
    float4 x = ((const float4*)in)[2 * idx];
    float4 y = ((const float4*)in)[2 * idx + 1];
    uint32_t h[4] = { packh2(x.x, x.y), packh2(x.z, x.w),
                      packh2(y.x, y.y), packh2(y.z, y.w) };
    ((uint4*)out)[idx] = *(uint4*)h;
}

// ---------------------------------------------------------------------------
// Fused-convert GEMM core (round-10 proven version)
// ---------------------------------------------------------------------------
#define LDG_A(areg, Ap, kc) do {                                             \
    _Pragma("unroll")                                                        \
    for (int u = 0; u < 16; u++) {                                           \
        int row = u * 8 + (tid >> 4);                                        \
        (areg)[u] = *(const float4*)((Ap) + (size_t)row * DD + (kc) * 64     \
                                     + (tid & 15) * 4);                      \
    }                                                                        \
} while (0)

#define STS_A(areg, sbase) do {                                              \
    _Pragma("unroll")                                                        \
    for (int u = 0; u < 16; u++) {                                           \
        int row = u * 8 + (tid >> 4);                                        \
        int c4 = tid & 15;                                                   \
        int ch = c4 >> 1;                                                    \
        uint32_t off = (uint32_t)(row * 128 + ((ch ^ (row & 7)) << 4)        \
                                  + (c4 & 1) * 8);                           \
        uint2 hv;                                                            \
        hv.x = packh2((areg)[u].x, (areg)[u].y);                             \
        hv.y = packh2((areg)[u].z, (areg)[u].w);                             \
        *(uint2*)((char*)sm + (sbase) + off) = hv;                           \
    }                                                                        \
} while (0)

#define LD_B(Bp, kc, sbase) do {                                             \
    const __half* gb = (Bp) + (kc) * 64;                                     \
    _Pragma("unroll")                                                        \
    for (int u = 0; u < 8; u++) {                                            \
        int idx = u * 128 + tid;                                             \
        int row = idx >> 3, ch = idx & 7;                                    \
        uint32_t off = (uint32_t)(row * 128 + ((ch ^ (row & 7)) << 4));      \
        cp16(smb + (sbase) + off, gb + (size_t)row * DD + ch * 8);           \
    }                                                                        \
    CP_COMMIT();                                                             \
} while (0)

#define GEMM_MAIN(Ap, Bp)                                                    \
    float4 areg[16];                                                         \
    float acc[4][8][4];                                                      \
    _Pragma("unroll")                                                        \
    for (int mt = 0; mt < 4; mt++)                                           \
        _Pragma("unroll")                                                    \
        for (int nt = 0; nt < 8; nt++)                                       \
            _Pragma("unroll")                                                \
            for (int i = 0; i < 4; i++) acc[mt][nt][i] = 0.f;                \
    LDG_A(areg, Ap, 0);                                                      \
    LD_B(Bp, 0, B_BASE);                                                     \
    LD_B(Bp, 1, B_BASE + A_STAGE);                                           \
    STS_A(areg, 0u);                                                         \
    LDG_A(areg, Ap, 1);                                                      \
    for (int kc = 0; kc < NKC; kc++) {                                       \
        if (kc < NKC - 1) { CP_WAIT(1); } else { CP_WAIT(0); }               \
        __syncthreads();                                                     \
        if (kc + 2 < NKC) {                                                  \
            int s2 = (kc + 2) % 3;                                           \
            LD_B(Bp, kc + 2, B_BASE + (uint32_t)s2 * A_STAGE);               \
        }                                                                    \
        uint32_t ab = smb + (uint32_t)(kc & 1) * A_STAGE;                    \
        uint32_t bb = smb + B_BASE + (uint32_t)(kc % 3) * A_STAGE;           \
        _Pragma("unroll")                                                    \
        for (int ks = 0; ks < 4; ks++) {                                     \
            uint32_t afr[4][4];                                              \
            _Pragma("unroll")                                                \
            for (int mt = 0; mt < 4; mt++) {                                 \
                int r = wm * 64 + mt * 16 + (lane & 15);                     \
                int c = ks * 2 + (lane >> 4);                                \
                ldsm4(afr[mt], ab + r * 128 + ((c ^ (r & 7)) << 4));         \
            }                                                                \
            _Pragma("unroll")                                                \
            for (int eb = 0; eb < 4; eb++) {                                 \
                int r = wn * 64 + eb * 16 + ((lane >> 4) << 3) + (lane & 7); \
                int c = ks * 2 + ((lane >> 3) & 1);                          \
                uint32_t bfr[4];                                             \
                ldsm4(bfr, bb + r * 128 + ((c ^ (r & 7)) << 4));             \
                _Pragma("unroll")                                            \
                for (int mt = 0; mt < 4; mt++) {                             \
                    mma16(acc[mt][eb * 2],     afr[mt], bfr);                \
                    mma16(acc[mt][eb * 2 + 1], afr[mt], bfr + 2);            \
                }                                                            \
            }                                                                \
        }                                                                    \
        if (kc + 1 < NKC) {                                                  \
            STS_A(areg, (uint32_t)((kc + 1) & 1) * A_STAGE);                 \
            if (kc + 2 < NKC) LDG_A(areg, Ap, kc + 2);                       \
        }                                                                    \
    }

// ---------------------------------------------------------------------------
// K+V projection GEMM (half-batch launch): grid (16, 128); rbase selects rows.
// ---------------------------------------------------------------------------
__global__ __launch_bounds__(128, 2)
void gemm_kv(const float* __restrict__ kin, const float* __restrict__ vin,
             const float* __restrict__ bk, const float* __restrict__ gK,
             const float* __restrict__ beK, const float* __restrict__ bv,
             const float* __restrict__ gV, const float* __restrict__ beV,
             int rbase)
{
    extern __shared__ float sm[];
    const int jb2 = blockIdx.x;
    const int isV = jb2 >> 3;
    const int jb  = jb2 & 7;
    const int r0  = rbase + blockIdx.y * 128;
    const int b_  = r0 >> 13;
    const int tid = threadIdx.x;
    const int warp = tid >> 5, lane = tid & 31;
    const int wm = warp >> 1, wn = warp & 1;
    const int gid = lane >> 2, tig = lane & 3;

    const float* Ap = (isV ? vin : kin) + (size_t)r0 * DD;
    const __half* Bp = (isV ? g_hWv : g_hWk) + (size_t)jb * DK * DD;
    const float* bias  = isV ? bv  : bk;
    const float* gamma = isV ? gV  : gK;
    const float* beta  = isV ? beV : beK;
    const uint32_t smb = smem_u32(sm);

    GEMM_MAIN(Ap, Bp)

    float2 bv_[8], gv_[8], ev_[8];
    #pragma unroll
    for (int nt = 0; nt < 8; nt++) {
        int c = jb * DK + wn * 64 + nt * 8 + tig * 2;
        bv_[nt] = *(const float2*)&bias[c];
        gv_[nt] = *(const float2*)&gamma[c];
        ev_[nt] = *(const float2*)&beta[c];
    }
    float s_[4][2], ss_[4][2];
    #pragma unroll
    for (int mt = 0; mt < 4; mt++)
        #pragma unroll
        for (int h = 0; h < 2; h++) { s_[mt][h] = 0.f; ss_[mt][h] = 0.f; }

    #pragma unroll
    for (int mt = 0; mt < 4; mt++)
        #pragma unroll
        for (int nt = 0; nt < 8; nt++) {
            acc[mt][nt][0] += bv_[nt].x; acc[mt][nt][1] += bv_[nt].y;
            acc[mt][nt][2] += bv_[nt].x; acc[mt][nt][3] += bv_[nt].y;
            #pragma unroll
            for (int h = 0; h < 2; h++) {
                float x0 = acc[mt][nt][2 * h], x1 = acc[mt][nt][2 * h + 1];
                s_[mt][h]  += x0 + x1;
                ss_[mt][h] += x0 * x0 + x1 * x1;
            }
        }
    #pragma unroll
    for (int mt = 0; mt < 4; mt++)
        #pragma unroll
        for (int h = 0; h < 2; h++) {
            #pragma unroll
            for (int o = 1; o <= 2; o <<= 1) {
                s_[mt][h]  += __shfl_xor_sync(0xFFFFFFFFu, s_[mt][h],  o);
                ss_[mt][h] += __shfl_xor_sync(0xFFFFFFFFu, ss_[mt][h], o);
            }
        }

    __syncthreads();
    float* red = sm;
    if (tig == 0) {
        #pragma unroll
        for (int mt = 0; mt < 4; mt++)
            #pragma unroll
            for (int h = 0; h < 2; h++) {
                int row = wm * 64 + mt * 16 + gid + h * 8;
                red[(row * 2 + wn) * 2 + 0] = s_[mt][h];
                red[(row * 2 + wn) * 2 + 1] = ss_[mt][h];
            }
    }
    __syncthreads();

    __half* dst = isV ? g_Vnh : g_Knh;
    #pragma unroll
    for (int mt = 0; mt < 4; mt++)
        #pragma unroll
        for (int h = 0; h < 2; h++) {
            int row = wm * 64 + mt * 16 + gid + h * 8;
            float st_ = red[(row * 2 + 0) * 2 + 0] + red[(row * 2 + 1) * 2 + 0];
            float sst = red[(row * 2 + 0) * 2 + 1] + red[(row * 2 + 1) * 2 + 1];
            float mean = st_ * (1.f / DK);
            float var  = sst * (1.f / DK) - mean * mean;
            float inv  = rsqrtf(var + EPSF);
            int r  = r0 + row;
            __half* op = dst + (((size_t)(b_ * HH + jb)) * NN + (r & (NN - 1))) * DK;
            #pragma unroll
            for (int nt = 0; nt < 8; nt++) {
                float ox = (acc[mt][nt][2*h+0] - mean) * inv * gv_[nt].x + ev_[nt].x;
                float oy = (acc[mt][nt][2*h+1] - mean) * inv * gv_[nt].y + ev_[nt].y;
                uint32_t pk = packh2(ox, oy);
                *(uint32_t*)(op + wn * 64 + nt * 8 + tig * 2) = pk;
            }
        }
}

// ---------------------------------------------------------------------------
// final GEMM (all batches): grid (8, 256)
// ---------------------------------------------------------------------------
__global__ __launch_bounds__(128, 2)
void gemm_fin(const float* __restrict__ qin, float* __restrict__ outp)
{
    extern __shared__ float sm[];
    const int jb  = blockIdx.x;
    const int r0  = blockIdx.y * 128;
    const int b_  = r0 >> 13;
    const int tid = threadIdx.x;
    const int warp = tid >> 5, lane = tid & 31;
    const int wm = warp >> 1, wn = warp & 1;
    const int gid = lane >> 2, tig = lane & 3;

    const float* Ap = qin + (size_t)r0 * DD;
    const __half* Bp = g_WeffTh + (size_t)b_ * DD * DD + (size_t)jb * DK * DD;
    const uint32_t smb = smem_u32(sm);

    GEMM_MAIN(Ap, Bp)

    float2 bev[8];
    #pragma unroll
    for (int nt = 0; nt < 8; nt++)
        bev[nt] = *(const float2*)&g_beff[(size_t)b_ * DD + jb * DK
                                          + wn * 64 + nt * 8 + tig * 2];
    #pragma unroll
    for (int mt = 0; mt < 4; mt++)
        #pragma unroll
        for (int h = 0; h < 2; h++) {
            int row = wm * 64 + mt * 16 + gid + h * 8;
            float* op = outp + (size_t)(r0 + row) * DD + jb * DK;
            #pragma unroll
            for (int nt = 0; nt < 8; nt++) {
                float2 o;
                o.x = acc[mt][nt][2 * h + 0] + bev[nt].x;
                o.y = acc[mt][nt][2 * h + 1] + bev[nt].y;
                *(float2*)(op + wn * 64 + nt * 8 + tig * 2) = o;
            }
        }
}

// ---------------------------------------------------------------------------
// scores (half-batch): grid (SPLITS, 16); bh = bh_base + blockIdx.y
// ---------------------------------------------------------------------------
__global__ __launch_bounds__(256)
void scores_h(int bh_base)
{
    extern __shared__ float sm[];
    const int split = blockIdx.x;
    const int bh    = bh_base + blockIdx.y;
    const int tid = threadIdx.x;
    const int warp = tid >> 5, lane = tid & 31;
    const int wm = warp >> 1, wn = warp & 1;
    const int gid = lane >> 2, tig = lane & 3;

    const size_t base = (size_t)bh * NN * DK + (size_t)split * CHS * DK;
    const uint32_t smb = smem_u32(sm);

    float acc[2][8][4];
    #pragma unroll
    for (int mt = 0; mt < 2; mt++)
        #pragma unroll
        for (int nt = 0; nt < 8; nt++)
            #pragma unroll
            for (int i = 0; i < 4; i++) acc[mt][nt][i] = 0.f;

    auto load_stage = [&](int kc, int s) {
        uint32_t kb = smb + (uint32_t)s * 16384u;
        const __half* gk = g_Knh + base + (size_t)kc * 32 * DK;
        const __half* gv = g_Vnh + base + (size_t)kc * 32 * DK;
        #pragma unroll
        for (int u = 0; u < 2; u++) {
            int idx = u * 256 + tid;
            int row = idx >> 4, ch = idx & 15;
            uint32_t off = (uint32_t)(row * 256 + ((ch ^ (row & 7)) << 4));
            cp16(kb + off,          gk + (size_t)row * DK + ch * 8);
            cp16(kb + 8192u + off,  gv + (size_t)row * DK + ch * 8);
        }
        CP_COMMIT();
    };

    const int NCH = CHS / 32;
    load_stage(0, 0);
    load_stage(1, 1);

    for (int kc = 0; kc < NCH; kc++) {
        if (kc < NCH - 1) { CP_WAIT(1); } else { CP_WAIT(0); }
        __syncthreads();
        if (kc + 2 < NCH) load_stage(kc + 2, (kc + 2) % 3);

        uint32_t kb = smb + (uint32_t)(kc % 3) * 16384u;
        uint32_t vb = kb + 8192u;
        #pragma unroll
        for (int step = 0; step < 2; step++) {
            int n0 = step * 16;
            uint32_t afr[2][4];
            #pragma unroll
            for (int mt = 0; mt < 2; mt++) {
                int m0 = wm * 32 + mt * 16;
                int r = n0 + ((lane >> 4) << 3) + (lane & 7);
                int c = (m0 >> 3) + ((lane >> 3) & 1);
                ldsm4t(afr[mt], kb + r * 256 + ((c ^ (r & 7)) << 4));
            }
            #pragma unroll
            for (int eb = 0; eb < 4; eb++) {
                int e0 = wn * 64 + eb * 16;
                int r = n0 + (((lane >> 3) & 1) << 3) + (lane & 7);
                int c = (e0 >> 3) + (lane >> 4);
                uint32_t bfr[4];
                ldsm4t(bfr, vb + r * 256 + ((c ^ (r & 7)) << 4));
                mma16(acc[0][eb * 2],     afr[0], bfr);
                mma16(acc[0][eb * 2 + 1], afr[0], bfr + 2);
                mma16(acc[1][eb * 2],     afr[1], bfr);
                mma16(acc[1][eb * 2 + 1], afr[1], bfr + 2);
            }
        }
    }

    size_t pbase = ((size_t)split * (BB * HH) + bh) * DK * DK;
    #pragma unroll
    for (int mt = 0; mt < 2; mt++)
        #pragma unroll
        for (int h = 0; h < 2; h++) {
            int row = wm * 32 + mt * 16 + gid + h * 8;
            #pragma unroll
            for (int nt = 0; nt < 8; nt++) {
                float2 o;
                o.x = acc[mt][nt][2 * h + 0];
                o.y = acc[mt][nt][2 * h + 1];
                *(float2*)&g_Spart[pbase + (size_t)row * DK
                                   + wn * 64 + nt * 8 + tig * 2] = o;
            }
        }
}

// ---------------------------------------------------------------------------
// reduce (half-batch): grid 256 x 256 thr; handles 16 bh worth of p
// ---------------------------------------------------------------------------
__global__ __launch_bounds__(256)
void reduce_scores_kernel(float* __restrict__ p_out, int bh_base)
{
    int i4 = blockIdx.x * 256 + threadIdx.x;          // < 16*DK*DK/4
    size_t base4 = (size_t)bh_base * (DK * DK / 4);
    const float4* sp = (const float4*)g_Spart;
    float4 s = sp[base4 + i4];
    #pragma unroll
    for (int spt = 1; spt < SPLITS; spt++) {
        float4 t = sp[(size_t)spt * (BB * HH * DK * DK / 4) + base4 + i4];
        s.x += t.x; s.y += t.y; s.z += t.z; s.w += t.w;
    }
    const float inv = 1.f / NN;
    s.x *= inv; s.y *= inv; s.z *= inv; s.w *= inv;
    ((float4*)p_out)[base4 + i4] = s;
}

// ---------------------------------------------------------------------------
// weff (half-batch) with fused beff: grid (16, 16); bh = bh_base + y.
// Block c0==0 additionally computes beff[e] = sum_d bq[h,d] * p[d,e].
// ---------------------------------------------------------------------------
__global__ __launch_bounds__(256)
void weff_kernel(const float* __restrict__ Wq, const float* __restrict__ bq,
                 const float* __restrict__ p, int bh_base)
{
    const int c0 = blockIdx.x * 64;
    const int bh = bh_base + blockIdx.y;
    const int h = bh & (HH - 1), b_ = bh >> 3;
    const int tid = threadIdx.x;
    const int ty = tid >> 4, tx = tid & 15;

    __shared__ float As[16][64];
    __shared__ float Bs[16][128];

    float acc[4][8];
    #pragma unroll
    for (int i = 0; i < 4; i++)
        #pragma unroll
        for (int j = 0; j < 8; j++) acc[i][j] = 0.f;

    float bacc = 0.f;

    const int ak = tid >> 4;
    const int ar = (tid & 15) * 4;
    const int bk = tid >> 4;
    const int bc = (tid & 15) * 8;

    for (int k0 = 0; k0 < DK; k0 += 16) {
        *(float4*)&As[ak][ar] =
            *(const float4*)&Wq[(size_t)(h * DK + k0 + ak) * DD + c0 + ar];
        const float* pp = &p[(size_t)bh * DK * DK + (size_t)(k0 + bk) * DK + bc];
        *(float4*)&Bs[bk][bc]     = *(const float4*)pp;
        *(float4*)&Bs[bk][bc + 4] = *(const float4*)(pp + 4);
        __syncthreads();

        #pragma unroll
        for (int kk = 0; kk < 16; kk++) {
            float a[4], b[8];
            *(float4*)a       = *(const float4*)&As[kk][ty * 4];
            *(float4*)b       = *(const float4*)&Bs[kk][tx * 8];
            *(float4*)(b + 4) = *(const float4*)&Bs[kk][tx * 8 + 4];
            #pragma unroll
            for (int i = 0; i < 4; i++)
                #pragma unroll
                for (int j = 0; j < 8; j++) acc[i][j] += a[i] * b[j];
        }
        if (blockIdx.x == 0 && tid < DK) {
            #pragma unroll
            for (int kk = 0; kk < 16; kk++)
                bacc += bq[h * DK + k0 + kk] * Bs[kk][tid];
        }
        __syncthreads();
    }

    #pragma unroll
    for (int i = 0; i < 4; i++)
        #pragma unroll
        for (int j = 0; j < 8; j++)
            g_WeffTh[(size_t)b_ * DD * DD
                     + (size_t)(h * DK + tx * 8 + j) * DD + (c0 + ty * 4 + i)]
                = __float2half_rn(acc[i][j]);

    if (blockIdx.x == 0 && tid < DK)
        g_beff[(size_t)b_ * DD + h * DK + tid] = bacc;
}

extern "C" void kernel_launch(void* const* d_in, const int* in_sizes, int n_in,
                              void* d_out, int out_size)
{
    const float* q   = (const float*)d_in[0];
    const float* k   = (const float*)d_in[1];
    const float* v   = (const float*)d_in[2];
    const float* Wq  = (const float*)d_in[3];
    const float* bq  = (const float*)d_in[4];
    const float* Wk  = (const float*)d_in[5];
    const float* bk  = (const float*)d_in[6];
    const float* Wv  = (const float*)d_in[7];
    const float* bv  = (const float*)d_in[8];
    const float* gK  = (const float*)d_in[9];
    const float* beK = (const float*)d_in[10];
    const float* gV  = (const float*)d_in[11];
    const float* beV = (const float*)d_in[12];

    float* out   = (float*)d_out;
    float* p_out = out + (size_t)BN * DD;

    static bool init_done = false;
    static cudaStream_t s1;
    static cudaEvent_t evA, evB, evW;
    if (!init_done) {
        cudaFuncSetAttribute(gemm_kv,  cudaFuncAttributeMaxDynamicSharedMemorySize, GEMM_SMEM);
        cudaFuncSetAttribute(gemm_fin, cudaFuncAttributeMaxDynamicSharedMemorySize, GEMM_SMEM);
        cudaFuncSetAttribute(scores_h, cudaFuncAttributeMaxDynamicSharedMemorySize, SC_SMEM);
        cudaStreamCreateWithFlags(&s1, cudaStreamNonBlocking);
        cudaEventCreateWithFlags(&evA, cudaEventDisableTiming);
        cudaEventCreateWithFlags(&evB, cudaEventDisableTiming);
        cudaEventCreateWithFlags(&evW, cudaEventDisableTiming);
        init_done = true;
    }

    const int n8_w = (DD * DD) / 8;
    f2h_w<<<(2 * n8_w) / 256, 256>>>(Wk, Wv, n8_w);

    // half 1: batches 0-1 (rows 0..16383, bh 0..15)
    gemm_kv<<<dim3(2 * HH, 128), 128, GEMM_SMEM>>>(k, v, bk, gK, beK, bv, gV, beV, 0);
    cudaEventRecord(evA, 0);

    // chain for half 1 on side stream, overlapped with half-2 gemm_kv
    cudaStreamWaitEvent(s1, evA, 0);
    scores_h<<<dim3(SPLITS, 16), 256, SC_SMEM, s1>>>(0);
    reduce_scores_kernel<<<256, 256, 0, s1>>>(p_out, 0);
    weff_kernel<<<dim3(DD / 64, 16), 256, 0, s1>>>(Wq, bq, p_out, 0);

    // half 2: batches 2-3
    gemm_kv<<<dim3(2 * HH, 128), 128, GEMM_SMEM>>>(k, v, bk, gK, beK, bv, gV, beV, 16384);
    cudaEventRecord(evB, 0);

    cudaStreamWaitEvent(s1, evB, 0);
    scores_h<<<dim3(SPLITS, 16), 256, SC_SMEM, s1>>>(16);
    reduce_scores_kernel<<<256, 256, 0, s1>>>(p_out, 16);
    weff_kernel<<<dim3(DD / 64, 16), 256, 0, s1>>>(Wq, bq, p_out, 16);
    cudaEventRecord(evW, s1);

    cudaStreamWaitEvent(0, evW, 0);
    gemm_fin<<<dim3(HH, 256), 128, GEMM_SMEM>>>(q, out);
}

// round 16
// speedup vs baseline: 1.0165x; 1.0165x over previous
#include <cuda_runtime.h>
#include <cuda_fp16.h>
#include <cstdint>

#define BB 4
#define NN 8192
#define DD 1024
#define HH 8
#define DK 128
#define BN (BB*NN)
#define SPLITS 16
#define CHS (NN/SPLITS)
#define EPSF 1e-5f
#define NKC (DD/64)
#define A_STAGE 16384u
#define B_BASE  32768u
#define GEMM_SMEM 81920
#define SC_SMEM  49152

// Scratch (allocation-free device globals)
__device__ __half g_hWk[(size_t)DD*DD];
__device__ __half g_hWv[(size_t)DD*DD];
__device__ __half g_Knh[(size_t)BB*HH*NN*DK];
__device__ __half g_Vnh[(size_t)BB*HH*NN*DK];
__device__ float  g_Spart[(size_t)SPLITS*BB*HH*DK*DK];
__device__ __half g_WeffTh[(size_t)BB*DD*DD];
__device__ float  g_beff[(size_t)BB*DD];

// ---------------------------------------------------------------------------
__device__ __forceinline__ uint32_t smem_u32(const void* p) {
    uint32_t a;
    asm("{ .reg .u64 t; cvta.to.shared.u64 t, %1; cvt.u32.u64 %0, t; }"
        : "=r"(a) : "l"(p));
    return a;
}
__device__ __forceinline__ void cp16(uint32_t smem, const void* g) {
    asm volatile("cp.async.cg.shared.global [%0], [%1], 16;"
                 :: "r"(smem), "l"(g));
}
#define CP_COMMIT() asm volatile("cp.async.commit_group;" ::: "memory")
#define CP_WAIT(n)  asm volatile("cp.async.wait_group %0;" :: "n"(n) : "memory")

__device__ __forceinline__ void ldsm4(uint32_t* r, uint32_t a) {
    asm volatile("ldmatrix.sync.aligned.m8n8.x4.shared.b16 {%0,%1,%2,%3}, [%4];"
                 : "=r"(r[0]), "=r"(r[1]), "=r"(r[2]), "=r"(r[3]) : "r"(a));
}
__device__ __forceinline__ void ldsm4t(uint32_t* r, uint32_t a) {
    asm volatile("ldmatrix.sync.aligned.m8n8.x4.trans.shared.b16 {%0,%1,%2,%3}, [%4];"
                 : "=r"(r[0]), "=r"(r[1]), "=r"(r[2]), "=r"(r[3]) : "r"(a));
}
__device__ __forceinline__ void mma16(float* d, const uint32_t* a, const uint32_t* b) {
    asm volatile(
        "mma.sync.aligned.m16n8k16.row.col.f32.f16.f16.f32 "
        "{%0,%1,%2,%3}, {%4,%5,%6,%7}, {%8,%9}, {%0,%1,%2,%3};"
        : "+f"(d[0]), "+f"(d[1]), "+f"(d[2]), "+f"(d[3])
        : "r"(a[0]), "r"(a[1]), "r"(a[2]), "r"(a[3]), "r"(b[0]), "r"(b[1]));
}
__device__ __forceinline__ uint32_t packh2(float x, float y) {
    uint32_t r;
    asm("cvt.rn.f16x2.f32 %0, %2, %1;" : "=r"(r) : "f"(x), "f"(y));
    return r;
}

// ---------------------------------------------------------------------------
__global__ __launch_bounds__(256)
void f2h_w(const float* __restrict__ Wk, const float* __restrict__ Wv, int n8)
{
    int i = blockIdx.x * 256 + threadIdx.x;
    const float* in = (i < n8) ? Wk : Wv;
    __half* out = (i < n8) ? g_hWk : g_hWv;
    int idx = (i < n8) ? i : i - n8;
    float4 x = ((const float4*)in)[2 * idx];
    float4 y = ((const float4*)in)[2 * idx + 1];
    uint32_t h[4] = { packh2(x.x, x.y), packh2(x.z, x.w),
                      packh2(y.x, y.y), packh2(y.z, y.w) };
    ((uint4*)out)[idx] = *(uint4*)h;
}

// ---------------------------------------------------------------------------
// Fused-convert GEMM core (round-10 proven version)
// ---------------------------------------------------------------------------
#define LDG_A(areg, Ap, kc) do {                                             \
    _Pragma("unroll")                                                        \
    for (int u = 0; u < 16; u++) {                                           \
        int row = u * 8 + (tid >> 4);                                        \
        (areg)[u] = *(const float4*)((Ap) + (size_t)row * DD + (kc) * 64     \
                                     + (tid & 15) * 4);                      \
    }                                                                        \
} while (0)

#define STS_A(areg, sbase) do {                                              \
    _Pragma("unroll")                                                        \
    for (int u = 0; u < 16; u++) {                                           \
        int row = u * 8 + (tid >> 4);                                        \
        int c4 = tid & 15;                                                   \
        int ch = c4 >> 1;                                                    \
        uint32_t off = (uint32_t)(row * 128 + ((ch ^ (row & 7)) << 4)        \
                                  + (c4 & 1) * 8);                           \
        uint2 hv;                                                            \
        hv.x = packh2((areg)[u].x, (areg)[u].y);                             \
        hv.y = packh2((areg)[u].z, (areg)[u].w);                             \
        *(uint2*)((char*)sm + (sbase) + off) = hv;                           \
    }                                                                        \
} while (0)

#define LD_B(Bp, kc, sbase) do {                                             \
    const __half* gb = (Bp) + (kc) * 64;                                     \
    _Pragma("unroll")                                                        \
    for (int u = 0; u < 8; u++) {                                            \
        int idx = u * 128 + tid;                                             \
        int row = idx >> 3, ch = idx & 7;                                    \
        uint32_t off = (uint32_t)(row * 128 + ((ch ^ (row & 7)) << 4));      \
        cp16(smb + (sbase) + off, gb + (size_t)row * DD + ch * 8);           \
    }                                                                        \
    CP_COMMIT();                                                             \
} while (0)

#define GEMM_MAIN(Ap, Bp)                                                    \
    float4 areg[16];                                                         \
    float acc[4][8][4];                                                      \
    _Pragma("unroll")                                                        \
    for (int mt = 0; mt < 4; mt++)                                           \
        _Pragma("unroll")                                                    \
        for (int nt = 0; nt < 8; nt++)                                       \
            _Pragma("unroll")                                                \
            for (int i = 0; i < 4; i++) acc[mt][nt][i] = 0.f;                \
    LDG_A(areg, Ap, 0);                                                      \
    LD_B(Bp, 0, B_BASE);                                                     \
    LD_B(Bp, 1, B_BASE + A_STAGE);                                           \
    STS_A(areg, 0u);                                                         \
    LDG_A(areg, Ap, 1);                                                      \
    for (int kc = 0; kc < NKC; kc++) {                                       \
        if (kc < NKC - 1) { CP_WAIT(1); } else { CP_WAIT(0); }               \
        __syncthreads();                                                     \
        if (kc + 2 < NKC) {                                                  \
            int s2 = (kc + 2) % 3;                                           \
            LD_B(Bp, kc + 2, B_BASE + (uint32_t)s2 * A_STAGE);               \
        }                                                                    \
        uint32_t ab = smb + (uint32_t)(kc & 1) * A_STAGE;                    \
        uint32_t bb = smb + B_BASE + (uint32_t)(kc % 3) * A_STAGE;           \
        _Pragma("unroll")                                                    \
        for (int ks = 0; ks < 4; ks++) {                                     \
            uint32_t afr[4][4];                                              \
            _Pragma("unroll")                                                \
            for (int mt = 0; mt < 4; mt++) {                                 \
                int r = wm * 64 + mt * 16 + (lane & 15);                     \
                int c = ks * 2 + (lane >> 4);                                \
                ldsm4(afr[mt], ab + r * 128 + ((c ^ (r & 7)) << 4));         \
            }                                                                \
            _Pragma("unroll")                                                \
            for (int eb = 0; eb < 4; eb++) {                                 \
                int r = wn * 64 + eb * 16 + ((lane >> 4) << 3) + (lane & 7); \
                int c = ks * 2 + ((lane >> 3) & 1);                          \
                uint32_t bfr[4];                                             \
                ldsm4(bfr, bb + r * 128 + ((c ^ (r & 7)) << 4));             \
                _Pragma("unroll")                                            \
                for (int mt = 0; mt < 4; mt++) {                             \
                    mma16(acc[mt][eb * 2],     afr[mt], bfr);                \
                    mma16(acc[mt][eb * 2 + 1], afr[mt], bfr + 2);            \
                }                                                            \
            }                                                                \
        }                                                                    \
        if (kc + 1 < NKC) {                                                  \
            STS_A(areg, (uint32_t)((kc + 1) & 1) * A_STAGE);                 \
            if (kc + 2 < NKC) LDG_A(areg, Ap, kc + 2);                       \
        }                                                                    \
    }

// ---------------------------------------------------------------------------
// K+V projection GEMM: grid (16, 256); x: 0-7 K heads, 8-15 V heads.
// ---------------------------------------------------------------------------
__global__ __launch_bounds__(128, 2)
void gemm_kv(const float* __restrict__ kin, const float* __restrict__ vin,
             const float* __restrict__ bk, const float* __restrict__ gK,
             const float* __restrict__ beK, const float* __restrict__ bv,
             const float* __restrict__ gV, const float* __restrict__ beV)
{
    extern __shared__ float sm[];
    const int jb2 = blockIdx.x;
    const int isV = jb2 >> 3;
    const int jb  = jb2 & 7;
    const int r0  = blockIdx.y * 128;
    const int b_  = r0 >> 13;
    const int tid = threadIdx.x;
    const int warp = tid >> 5, lane = tid & 31;
    const int wm = warp >> 1, wn = warp & 1;
    const int gid = lane >> 2, tig = lane & 3;

    const float* Ap = (isV ? vin : kin) + (size_t)r0 * DD;
    const __half* Bp = (isV ? g_hWv : g_hWk) + (size_t)jb * DK * DD;
    const float* bias  = isV ? bv  : bk;
    const float* gamma = isV ? gV  : gK;
    const float* beta  = isV ? beV : beK;
    const uint32_t smb = smem_u32(sm);

    GEMM_MAIN(Ap, Bp)

    float2 bv_[8], gv_[8], ev_[8];
    #pragma unroll
    for (int nt = 0; nt < 8; nt++) {
        int c = jb * DK + wn * 64 + nt * 8 + tig * 2;
        bv_[nt] = *(const float2*)&bias[c];
        gv_[nt] = *(const float2*)&gamma[c];
        ev_[nt] = *(const float2*)&beta[c];
    }
    float s_[4][2], ss_[4][2];
    #pragma unroll
    for (int mt = 0; mt < 4; mt++)
        #pragma unroll
        for (int h = 0; h < 2; h++) { s_[mt][h] = 0.f; ss_[mt][h] = 0.f; }

    #pragma unroll
    for (int mt = 0; mt < 4; mt++)
        #pragma unroll
        for (int nt = 0; nt < 8; nt++) {
            acc[mt][nt][0] += bv_[nt].x; acc[mt][nt][1] += bv_[nt].y;
            acc[mt][nt][2] += bv_[nt].x; acc[mt][nt][3] += bv_[nt].y;
            #pragma unroll
            for (int h = 0; h < 2; h++) {
                float x0 = acc[mt][nt][2 * h], x1 = acc[mt][nt][2 * h + 1];
                s_[mt][h]  += x0 + x1;
                ss_[mt][h] += x0 * x0 + x1 * x1;
            }
        }
    #pragma unroll
    for (int mt = 0; mt < 4; mt++)
        #pragma unroll
        for (int h = 0; h < 2; h++) {
            #pragma unroll
            for (int o = 1; o <= 2; o <<= 1) {
                s_[mt][h]  += __shfl_xor_sync(0xFFFFFFFFu, s_[mt][h],  o);
                ss_[mt][h] += __shfl_xor_sync(0xFFFFFFFFu, ss_[mt][h], o);
            }
        }

    __syncthreads();
    float* red = sm;
    if (tig == 0) {
        #pragma unroll
        for (int mt = 0; mt < 4; mt++)
            #pragma unroll
            for (int h = 0; h < 2; h++) {
                int row = wm * 64 + mt * 16 + gid + h * 8;
                red[(row * 2 + wn) * 2 + 0] = s_[mt][h];
                red[(row * 2 + wn) * 2 + 1] = ss_[mt][h];
            }
    }
    __syncthreads();

    __half* dst = isV ? g_Vnh : g_Knh;
    #pragma unroll
    for (int mt = 0; mt < 4; mt++)
        #pragma unroll
        for (int h = 0; h < 2; h++) {
            int row = wm * 64 + mt * 16 + gid + h * 8;
            float st_ = red[(row * 2 + 0) * 2 + 0] + red[(row * 2 + 1) * 2 + 0];
            float sst = red[(row * 2 + 0) * 2 + 1] + red[(row * 2 + 1) * 2 + 1];
            float mean = st_ * (1.f / DK);
            float var  = sst * (1.f / DK) - mean * mean;
            float inv  = rsqrtf(var + EPSF);
            int r  = r0 + row;
            __half* op = dst + (((size_t)(b_ * HH + jb)) * NN + (r & (NN - 1))) * DK;
            #pragma unroll
            for (int nt = 0; nt < 8; nt++) {
                float ox = (acc[mt][nt][2*h+0] - mean) * inv * gv_[nt].x + ev_[nt].x;
                float oy = (acc[mt][nt][2*h+1] - mean) * inv * gv_[nt].y + ev_[nt].y;
                uint32_t pk = packh2(ox, oy);
                *(uint32_t*)(op + wn * 64 + nt * 8 + tig * 2) = pk;
            }
        }
}

// ---------------------------------------------------------------------------
// final GEMM: grid (8, 256)
// ---------------------------------------------------------------------------
__global__ __launch_bounds__(128, 2)
void gemm_fin(const float* __restrict__ qin, float* __restrict__ outp)
{
    extern __shared__ float sm[];
    const int jb  = blockIdx.x;
    const int r0  = blockIdx.y * 128;
    const int b_  = r0 >> 13;
    const int tid = threadIdx.x;
    const int warp = tid >> 5, lane = tid & 31;
    const int wm = warp >> 1, wn = warp & 1;
    const int gid = lane >> 2, tig = lane & 3;

    const float* Ap = qin + (size_t)r0 * DD;
    const __half* Bp = g_WeffTh + (size_t)b_ * DD * DD + (size_t)jb * DK * DD;
    const uint32_t smb = smem_u32(sm);

    GEMM_MAIN(Ap, Bp)

    float2 bev[8];
    #pragma unroll
    for (int nt = 0; nt < 8; nt++)
        bev[nt] = *(const float2*)&g_beff[(size_t)b_ * DD + jb * DK
                                          + wn * 64 + nt * 8 + tig * 2];
    #pragma unroll
    for (int mt = 0; mt < 4; mt++)
        #pragma unroll
        for (int h = 0; h < 2; h++) {
            int row = wm * 64 + mt * 16 + gid + h * 8;
            float* op = outp + (size_t)(r0 + row) * DD + jb * DK;
            #pragma unroll
            for (int nt = 0; nt < 8; nt++) {
                float2 o;
                o.x = acc[mt][nt][2 * h + 0] + bev[nt].x;
                o.y = acc[mt][nt][2 * h + 1] + bev[nt].y;
                *(float2*)(op + wn * 64 + nt * 8 + tig * 2) = o;
            }
        }
}

// ---------------------------------------------------------------------------
// scores: 3-stage cp.async, ONE sync per 32-row chunk; SPLITS=16.
// ---------------------------------------------------------------------------
__global__ __launch_bounds__(256)
void scores_h()
{
    extern __shared__ float sm[];
    const int split = blockIdx.x;
    const int bh    = blockIdx.y;
    const int tid = threadIdx.x;
    const int warp = tid >> 5, lane = tid & 31;
    const int wm = warp >> 1, wn = warp & 1;
    const int gid = lane >> 2, tig = lane & 3;

    const size_t base = (size_t)bh * NN * DK + (size_t)split * CHS * DK;
    const uint32_t smb = smem_u32(sm);

    float acc[2][8][4];
    #pragma unroll
    for (int mt = 0; mt < 2; mt++)
        #pragma unroll
        for (int nt = 0; nt < 8; nt++)
            #pragma unroll
            for (int i = 0; i < 4; i++) acc[mt][nt][i] = 0.f;

    auto load_stage = [&](int kc, int s) {
        uint32_t kb = smb + (uint32_t)s * 16384u;
        const __half* gk = g_Knh + base + (size_t)kc * 32 * DK;
        const __half* gv = g_Vnh + base + (size_t)kc * 32 * DK;
        #pragma unroll
        for (int u = 0; u < 2; u++) {
            int idx = u * 256 + tid;
            int row = idx >> 4, ch = idx & 15;
            uint32_t off = (uint32_t)(row * 256 + ((ch ^ (row & 7)) << 4));
            cp16(kb + off,          gk + (size_t)row * DK + ch * 8);
            cp16(kb + 8192u + off,  gv + (size_t)row * DK + ch * 8);
        }
        CP_COMMIT();
    };

    const int NCH = CHS / 32;
    load_stage(0, 0);
    load_stage(1, 1);

    for (int kc = 0; kc < NCH; kc++) {
        if (kc < NCH - 1) { CP_WAIT(1); } else { CP_WAIT(0); }
        __syncthreads();
        if (kc + 2 < NCH) load_stage(kc + 2, (kc + 2) % 3);

        uint32_t kb = smb + (uint32_t)(kc % 3) * 16384u;
        uint32_t vb = kb + 8192u;
        #pragma unroll
        for (int step = 0; step < 2; step++) {
            int n0 = step * 16;
            uint32_t afr[2][4];
            #pragma unroll
            for (int mt = 0; mt < 2; mt++) {
                int m0 = wm * 32 + mt * 16;
                int r = n0 + ((lane >> 4) << 3) + (lane & 7);
                int c = (m0 >> 3) + ((lane >> 3) & 1);
                ldsm4t(afr[mt], kb + r * 256 + ((c ^ (r & 7)) << 4));
            }
            #pragma unroll
            for (int eb = 0; eb < 4; eb++) {
                int e0 = wn * 64 + eb * 16;
                int r = n0 + (((lane >> 3) & 1) << 3) + (lane & 7);
                int c = (e0 >> 3) + (lane >> 4);
                uint32_t bfr[4];
                ldsm4t(bfr, vb + r * 256 + ((c ^ (r & 7)) << 4));
                mma16(acc[0][eb * 2],     afr[0], bfr);
                mma16(acc[0][eb * 2 + 1], afr[0], bfr + 2);
                mma16(acc[1][eb * 2],     afr[1], bfr);
                mma16(acc[1][eb * 2 + 1], afr[1], bfr + 2);
            }
        }
    }

    size_t pbase = ((size_t)split * (BB * HH) + bh) * DK * DK;
    #pragma unroll
    for (int mt = 0; mt < 2; mt++)
        #pragma unroll
        for (int h = 0; h < 2; h++) {
            int row = wm * 32 + mt * 16 + gid + h * 8;
            #pragma unroll
            for (int nt = 0; nt < 8; nt++) {
                float2 o;
                o.x = acc[mt][nt][2 * h + 0];
                o.y = acc[mt][nt][2 * h + 1];
                *(float2*)&g_Spart[pbase + (size_t)row * DK
                                   + wn * 64 + nt * 8 + tig * 2] = o;
            }
        }
}

// ---------------------------------------------------------------------------
// vectorized reduce over 16 splits
// ---------------------------------------------------------------------------
__global__ __launch_bounds__(256)
void reduce_scores_kernel(float* __restrict__ p_out)
{
    int i4 = blockIdx.x * 256 + threadIdx.x;   // < (B*H*DK*DK)/4
    const float4* sp = (const float4*)g_Spart;
    float4 s = sp[i4];
    #pragma unroll
    for (int spt = 1; spt < SPLITS; spt++) {
        float4 t = sp[(size_t)spt * (BB * HH * DK * DK / 4) + i4];
        s.x += t.x; s.y += t.y; s.z += t.z; s.w += t.w;
    }
    const float inv = 1.f / NN;
    s.x *= inv; s.y *= inv; s.z *= inv; s.w *= inv;
    ((float4*)p_out)[i4] = s;
}

// ---------------------------------------------------------------------------
// weff with fused beff: grid (16, 32).
// Block c0==0 also computes beff[e] = sum_d bq[h,d] * p[d,e].
// ---------------------------------------------------------------------------
__global__ __launch_bounds__(256)
void weff_kernel(const float* __restrict__ Wq, const float* __restrict__ bq,
                 const float* __restrict__ p)
{
    const int c0 = blockIdx.x * 64;
    const int bh = blockIdx.y;
    const int h = bh & (HH - 1), b_ = bh >> 3;
    const int tid = threadIdx.x;
    const int ty = tid >> 4, tx = tid & 15;

    __shared__ float As[16][64];
    __shared__ float Bs[16][128];

    float acc[4][8];
    #pragma unroll
    for (int i = 0; i < 4; i++)
        #pragma unroll
        for (int j = 0; j < 8; j++) acc[i][j] = 0.f;

    float bacc = 0.f;

    const int ak = tid >> 4;
    const int ar = (tid & 15) * 4;
    const int bk = tid >> 4;
    const int bc = (tid & 15) * 8;

    for (int k0 = 0; k0 < DK; k0 += 16) {
        *(float4*)&As[ak][ar] =
            *(const float4*)&Wq[(size_t)(h * DK + k0 + ak) * DD + c0 + ar];
        const float* pp = &p[(size_t)bh * DK * DK + (size_t)(k0 + bk) * DK + bc];
        *(float4*)&Bs[bk][bc]     = *(const float4*)pp;
        *(float4*)&Bs[bk][bc + 4] = *(const float4*)(pp + 4);
        __syncthreads();

        #pragma unroll
        for (int kk = 0; kk < 16; kk++) {
            float a[4], b[8];
            *(float4*)a       = *(const float4*)&As[kk][ty * 4];
            *(float4*)b       = *(const float4*)&Bs[kk][tx * 8];
            *(float4*)(b + 4) = *(const float4*)&Bs[kk][tx * 8 + 4];
            #pragma unroll
            for (int i = 0; i < 4; i++)
                #pragma unroll
                for (int j = 0; j < 8; j++) acc[i][j] += a[i] * b[j];
        }
        if (blockIdx.x == 0 && tid < DK) {
            #pragma unroll
            for (int kk = 0; kk < 16; kk++)
                bacc += bq[h * DK + k0 + kk] * Bs[kk][tid];
        }
        __syncthreads();
    }

    #pragma unroll
    for (int i = 0; i < 4; i++)
        #pragma unroll
        for (int j = 0; j < 8; j++)
            g_WeffTh[(size_t)b_ * DD * DD
                     + (size_t)(h * DK + tx * 8 + j) * DD + (c0 + ty * 4 + i)]
                = __float2half_rn(acc[i][j]);

    if (blockIdx.x == 0 && tid < DK)
        g_beff[(size_t)b_ * DD + h * DK + tid] = bacc;
}

extern "C" void kernel_launch(void* const* d_in, const int* in_sizes, int n_in,
                              void* d_out, int out_size)
{
    const float* q   = (const float*)d_in[0];
    const float* k   = (const float*)d_in[1];
    const float* v   = (const float*)d_in[2];
    const float* Wq  = (const float*)d_in[3];
    const float* bq  = (const float*)d_in[4];
    const float* Wk  = (const float*)d_in[5];
    const float* bk  = (const float*)d_in[6];
    const float* Wv  = (const float*)d_in[7];
    const float* bv  = (const float*)d_in[8];
    const float* gK  = (const float*)d_in[9];
    const float* beK = (const float*)d_in[10];
    const float* gV  = (const float*)d_in[11];
    const float* beV = (const float*)d_in[12];

    float* out   = (float*)d_out;
    float* p_out = out + (size_t)BN * DD;

    static bool init_done = false;
    if (!init_done) {
        cudaFuncSetAttribute(gemm_kv,  cudaFuncAttributeMaxDynamicSharedMemorySize, GEMM_SMEM);
        cudaFuncSetAttribute(gemm_fin, cudaFuncAttributeMaxDynamicSharedMemorySize, GEMM_SMEM);
        cudaFuncSetAttribute(scores_h, cudaFuncAttributeMaxDynamicSharedMemorySize, SC_SMEM);
        init_done = true;
    }

    const int n8_w = (DD * DD) / 8;
    f2h_w<<<(2 * n8_w) / 256, 256>>>(Wk, Wv, n8_w);

    gemm_kv<<<dim3(2 * HH, BN / 128), 128, GEMM_SMEM>>>(k, v, bk, gK, beK, bv, gV, beV);
    scores_h<<<dim3(SPLITS, BB * HH), 256, SC_SMEM>>>();
    reduce_scores_kernel<<<dim3((BB * HH * DK * DK) / 1024), 256>>>(p_out);
    weff_kernel<<<dim3(DD / 64, BB * HH), 256>>>(Wq, bq, p_out);
    gemm_fin<<<dim3(HH, BN / 128), 128, GEMM_SMEM>>>(q, out);
}